// round 5
// baseline (speedup 1.0000x reference)
#include <cuda_runtime.h>
#include <cuda_bf16.h>
#include <math.h>
#include <stdint.h>

// Problem dims (fixed by the dataset)
#define BQ 64
#define SQ 512
#define DQ 768
#define CQ 512
#define MQ (BQ*SQ)   // 32768 tokens
#define ZCH 8        // s-chunks for partial z

// ---------------- scratch (device globals; no allocation allowed) ----------
__device__ __nv_bfloat16 g_Vn[(size_t)MQ * DQ];   // normalized V, bf16 (48 MB)
__device__ __nv_bfloat16 g_Ln[(size_t)CQ * DQ];   // normalized labels, bf16
__device__ unsigned      g_mkey[MQ];              // ordered-uint encoded row max
__device__ float         g_beta[MQ];              // softmax weights
__device__ float         g_zpart[BQ * ZCH * DQ];  // partial z sums
__device__ float         g_z[BQ * DQ];            // z vectors

// ordered-uint encoding for float atomicMax (handles negatives)
__device__ __forceinline__ unsigned enc_f(float f) {
    unsigned u = __float_as_uint(f);
    return (u & 0x80000000u) ? ~u : (u | 0x80000000u);
}
__device__ __forceinline__ float dec_f(unsigned u) {
    return (u & 0x80000000u) ? __uint_as_float(u & 0x7fffffffu)
                             : __uint_as_float(~u);
}

// cp.async helpers
__device__ __forceinline__ void cpa16(void* smem, const void* g) {
    unsigned s = (unsigned)__cvta_generic_to_shared(smem);
    asm volatile("cp.async.cg.shared.global [%0], [%1], 16;\n" :: "r"(s), "l"(g));
}
#define CP_COMMIT() asm volatile("cp.async.commit_group;\n" ::: "memory")
#define CP_WAIT(n)  asm volatile("cp.async.wait_group %0;\n" :: "n"(n) : "memory")

__device__ __forceinline__ void ldsm_x4(unsigned& d0, unsigned& d1,
                                        unsigned& d2, unsigned& d3, const void* p) {
    unsigned a = (unsigned)__cvta_generic_to_shared(p);
    asm volatile("ldmatrix.sync.aligned.m8n8.x4.shared.b16 {%0,%1,%2,%3}, [%4];"
                 : "=r"(d0), "=r"(d1), "=r"(d2), "=r"(d3) : "r"(a));
}

// ---------------- kernel 1/2: row-normalize (warp per row) -----------------
__global__ void row_normalize_kernel(const float* __restrict__ in, int nrows, int mode) {
    int gw   = (blockIdx.x * blockDim.x + threadIdx.x) >> 5;
    int lane = threadIdx.x & 31;
    if (gw >= nrows) return;

    const float4* r = (const float4*)(in + (size_t)gw * DQ);
    float4 v[6];
    float ss = 0.f;
#pragma unroll
    for (int i = 0; i < 6; i++) {
        v[i] = r[lane + i * 32];
        ss += v[i].x * v[i].x + v[i].y * v[i].y + v[i].z * v[i].z + v[i].w * v[i].w;
    }
#pragma unroll
    for (int o = 16; o; o >>= 1) ss += __shfl_xor_sync(0xffffffffu, ss, o);
    float denom = fmaxf(sqrtf(ss), 1e-8f);
    float sc = 1.0f / denom;

    __nv_bfloat16* out = (mode ? g_Vn : g_Ln) + (size_t)gw * DQ;
#pragma unroll
    for (int i = 0; i < 6; i++) {
        int base = (lane + i * 32) * 4;
        __nv_bfloat162 p0 = __floats2bfloat162_rn(v[i].x * sc, v[i].y * sc);
        __nv_bfloat162 p1 = __floats2bfloat162_rn(v[i].z * sc, v[i].w * sc);
        uint2 pk;
        pk.x = *(unsigned*)&p0;
        pk.y = *(unsigned*)&p1;
        *(uint2*)(out + base) = pk;
    }
    if (mode && lane == 0) g_mkey[gw] = 0u;
}

// ---------------- kernel 3: bf16 GEMM (Vn @ Ln^T) + row max ---------------
// CTA 128x256, BK=32, 8 warps (warp tile 64x64), 3-stage cp.async pipeline,
// ldmatrix.x4 fragment loads. smem stride 40 bf16 -> conflict-free.
#define GSTRIDE  40
#define GSTAGE_A (128 * GSTRIDE)           // bf16 elems per A stage
#define GSTAGE_B (256 * GSTRIDE)           // bf16 elems per B stage
#define GK_SMEM  (3 * (GSTAGE_A + GSTAGE_B) * 2)   // 92160 bytes

__global__ __launch_bounds__(256, 1)
void gemm_rowmax_kernel() {
    extern __shared__ __nv_bfloat16 sm[];
    __nv_bfloat16* Asm = sm;                     // [3][128][40]
    __nv_bfloat16* Bsm = sm + 3 * GSTAGE_A;      // [3][256][40]
    __shared__ float rmax[128][4];

    const int bn = blockIdx.x;        // 0..1   (class tiles of 256)
    const int bm = blockIdx.y;        // 0..255 (token tiles of 128)
    const int t = threadIdx.x;        // 256 threads
    const int lane = t & 31, warp = t >> 5;
    const int wr = warp & 1, wc = warp >> 1;     // 2 x 4 warp grid
    const int wm0 = wr * 64, wn0 = wc * 64;
    const int g = lane >> 2, tq = lane & 3;
    // ldmatrix lane mapping
    const int row8 = lane & 7, tile = lane >> 3;
    const int tA_r = (tile & 1) * 8, tA_c = (tile >> 1) * 8;   // A: m-offset, k-offset
    const int tB_n = (tile >> 1) * 8, tB_c = (tile & 1) * 8;   // B: n-offset, k-offset

    float acc[4][8][4];
#pragma unroll
    for (int mi = 0; mi < 4; mi++)
#pragma unroll
        for (int ni = 0; ni < 8; ni++)
#pragma unroll
            for (int q = 0; q < 4; q++) acc[mi][ni][q] = 0.f;

    const size_t a_base = (size_t)(bm * 128) * DQ;
    const size_t b_base = (size_t)(bn * 256) * DQ;

    auto load_stage = [&](int st, int kt) {
        const int k0 = kt * 32;
        __nv_bfloat16* As = Asm + st * GSTAGE_A;
        __nv_bfloat16* Bs = Bsm + st * GSTAGE_B;
#pragma unroll
        for (int i = 0; i < 2; i++) {            // A: 512 chunks
            int idx = t + i * 256;
            int row = idx >> 2, ci = idx & 3;
            cpa16(&As[row * GSTRIDE + ci * 8],
                  &g_Vn[a_base + (size_t)row * DQ + k0 + ci * 8]);
        }
#pragma unroll
        for (int i = 0; i < 4; i++) {            // B: 1024 chunks
            int idx = t + i * 256;
            int row = idx >> 2, ci = idx & 3;
            cpa16(&Bs[row * GSTRIDE + ci * 8],
                  &g_Ln[b_base + (size_t)row * DQ + k0 + ci * 8]);
        }
        CP_COMMIT();
    };

    const int NK = DQ / 32;           // 24
    load_stage(0, 0);
    load_stage(1, 1);

    for (int kt = 0; kt < NK; kt++) {
        const int cur = kt % 3;
        if (kt + 1 < NK) CP_WAIT(1); else CP_WAIT(0);
        __syncthreads();

        const __nv_bfloat16* As = Asm + cur * GSTAGE_A;
        const __nv_bfloat16* Bs = Bsm + cur * GSTAGE_B;
#pragma unroll
        for (int kk = 0; kk < 32; kk += 16) {
            unsigned af[4][4], bf[8][2];
#pragma unroll
            for (int mi = 0; mi < 4; mi++) {
                ldsm_x4(af[mi][0], af[mi][1], af[mi][2], af[mi][3],
                        &As[(wm0 + mi * 16 + tA_r + row8) * GSTRIDE + kk + tA_c]);
            }
#pragma unroll
            for (int ni = 0; ni < 8; ni += 2) {
                ldsm_x4(bf[ni][0], bf[ni][1], bf[ni + 1][0], bf[ni + 1][1],
                        &Bs[(wn0 + ni * 8 + tB_n + row8) * GSTRIDE + kk + tB_c]);
            }
#pragma unroll
            for (int mi = 0; mi < 4; mi++)
#pragma unroll
                for (int ni = 0; ni < 8; ni++) {
                    asm volatile(
                        "mma.sync.aligned.m16n8k16.row.col.f32.bf16.bf16.f32 "
                        "{%0,%1,%2,%3}, {%4,%5,%6,%7}, {%8,%9}, {%0,%1,%2,%3};\n"
                        : "+f"(acc[mi][ni][0]), "+f"(acc[mi][ni][1]),
                          "+f"(acc[mi][ni][2]), "+f"(acc[mi][ni][3])
                        : "r"(af[mi][0]), "r"(af[mi][1]), "r"(af[mi][2]), "r"(af[mi][3]),
                          "r"(bf[ni][0]), "r"(bf[ni][1]));
                }
        }
        // refill buffer (kt+2)%3: last read in iter kt-1, ordered by this
        // iteration's __syncthreads.
        if (kt + 2 < NK) load_stage((kt + 2) % 3, kt + 2);
    }

    // per-row max over this 128x256 tile
#pragma unroll
    for (int mi = 0; mi < 4; mi++) {
        float lo = -INFINITY, hi = -INFINITY;
#pragma unroll
        for (int ni = 0; ni < 8; ni++) {
            lo = fmaxf(lo, fmaxf(acc[mi][ni][0], acc[mi][ni][1]));
            hi = fmaxf(hi, fmaxf(acc[mi][ni][2], acc[mi][ni][3]));
        }
        lo = fmaxf(lo, __shfl_xor_sync(0xffffffffu, lo, 1));
        lo = fmaxf(lo, __shfl_xor_sync(0xffffffffu, lo, 2));
        hi = fmaxf(hi, __shfl_xor_sync(0xffffffffu, hi, 1));
        hi = fmaxf(hi, __shfl_xor_sync(0xffffffffu, hi, 2));
        if (tq == 0) {
            if (wr == 0 || true) {
                rmax[wm0 + mi * 16 + g][wc]     = (wr == 0) ? lo : rmax[wm0 + mi * 16 + g][wc];
            }
            // direct write: each (row, wc) written by exactly one warp (wr picks rows)
            rmax[wm0 + mi * 16 + g][wc]     = lo;
            rmax[wm0 + mi * 16 + g + 8][wc] = hi;
        }
    }
    __syncthreads();
    if (t < 128) {
        float v = fmaxf(fmaxf(rmax[t][0], rmax[t][1]),
                        fmaxf(rmax[t][2], rmax[t][3]));
        atomicMax(&g_mkey[bm * 128 + t], enc_f(v));
    }
}

// ---------------- kernel 4a: softmax over S -> g_beta ----------------------
__global__ void beta_kernel() {
    __shared__ float red[16];
    const int b = blockIdx.x;
    const int t = threadIdx.x;
    const int lane = t & 31, wid = t >> 5;

    float m = dec_f(g_mkey[b * SQ + t]);
    float lm = m;
#pragma unroll
    for (int o = 16; o; o >>= 1) lm = fmaxf(lm, __shfl_xor_sync(0xffffffffu, lm, o));
    if (lane == 0) red[wid] = lm;
    __syncthreads();
    float M = red[0];
#pragma unroll
    for (int i = 1; i < 16; i++) M = fmaxf(M, red[i]);
    __syncthreads();

    float p = expf(m - M);
    float ls = p;
#pragma unroll
    for (int o = 16; o; o >>= 1) ls += __shfl_xor_sync(0xffffffffu, ls, o);
    if (lane == 0) red[wid] = ls;
    __syncthreads();
    float S = 0.f;
#pragma unroll
    for (int i = 0; i < 16; i++) S += red[i];

    g_beta[b * SQ + t] = p / S;
}

// ---------------- kernel 4b: partial z sums --------------------------------
__global__ void zpart_kernel(const float* __restrict__ V) {
    __shared__ float bsm[SQ / ZCH];
    const int b = blockIdx.x, ch = blockIdx.y;
    const int t = threadIdx.x;
    constexpr int RS = SQ / ZCH;   // 64 rows per chunk

    if (t < RS) bsm[t] = g_beta[b * SQ + ch * RS + t];
    __syncthreads();

    const float* Vb = V + ((size_t)b * SQ + ch * RS) * DQ;
    float a0 = 0.f, a1 = 0.f, a2 = 0.f;
#pragma unroll 4
    for (int r = 0; r < RS; r++) {
        float be = bsm[r];
        const float* row = Vb + (size_t)r * DQ;
        a0 += be * row[t];
        a1 += be * row[t + 256];
        a2 += be * row[t + 512];
    }
    float* zp = g_zpart + (size_t)(b * ZCH + ch) * DQ;
    zp[t]       = a0;
    zp[t + 256] = a1;
    zp[t + 512] = a2;
}

// ---------------- kernel 4c: combine partials -> z -------------------------
__global__ void zcombine_kernel(float* __restrict__ zout) {
    const int b = blockIdx.x;
    const int t = threadIdx.x;   // 256
#pragma unroll
    for (int j = 0; j < 3; j++) {
        int d = t + j * 256;
        float s = 0.f;
#pragma unroll
        for (int c = 0; c < ZCH; c++) s += g_zpart[(size_t)(b * ZCH + c) * DQ + d];
        g_z[b * DQ + d] = s;
        if (zout) zout[b * DQ + d] = s;
    }
}

// ---------------- kernel 5: out = z @ fc_w^T + fc_b ------------------------
__global__ void fc_kernel(const float* __restrict__ fc_w, const float* __restrict__ fc_b,
                          float* __restrict__ out) {
    const int t = threadIdx.x;
    const int lane = t & 31;
    const int gw = (blockIdx.x * blockDim.x + t) >> 5;
    if (gw >= BQ * CQ) return;
    const int b = gw >> 9;
    const int c = gw & 511;
    const float4* wr = (const float4*)(fc_w + (size_t)c * DQ);
    const float4* zr = (const float4*)(g_z + b * DQ);
    float acc = 0.f;
#pragma unroll
    for (int i = 0; i < 6; i++) {
        float4 wv = wr[lane + i * 32];
        float4 zv = zr[lane + i * 32];
        acc += wv.x * zv.x + wv.y * zv.y + wv.z * zv.z + wv.w * zv.w;
    }
#pragma unroll
    for (int o = 16; o; o >>= 1) acc += __shfl_xor_sync(0xffffffffu, acc, o);
    if (lane == 0) out[b * CQ + c] = acc + fc_b[c];
}

// ---------------- launch ----------------------------------------------------
extern "C" void kernel_launch(void* const* d_in, const int* in_sizes, int n_in,
                              void* d_out, int out_size) {
    const float* V  = (const float*)d_in[0];
    const float* L  = (const float*)d_in[1];
    const float* fw = (const float*)d_in[2];
    const float* fb = (const float*)d_in[3];
    float* out = (float*)d_out;
    float* zout = (out_size >= BQ * CQ + BQ * DQ) ? (out + BQ * CQ) : nullptr;

    static int smem_set = 0;
    if (!smem_set) {
        cudaFuncSetAttribute(gemm_rowmax_kernel,
                             cudaFuncAttributeMaxDynamicSharedMemorySize, GK_SMEM);
        smem_set = 1;
    }

    row_normalize_kernel<<<CQ / 8, 256>>>(L, CQ, 0);
    row_normalize_kernel<<<MQ / 8, 256>>>(V, MQ, 1);
    gemm_rowmax_kernel<<<dim3(CQ / 256, MQ / 128), 256, GK_SMEM>>>();
    beta_kernel<<<BQ, SQ>>>();
    zpart_kernel<<<dim3(BQ, ZCH), 256>>>(V);
    zcombine_kernel<<<BQ, 256>>>(zout);
    fc_kernel<<<(BQ * CQ * 32) / 256, 256>>>(fw, fb, out);
}

// round 6
// speedup vs baseline: 1.1264x; 1.1264x over previous
#include <cuda_runtime.h>
#include <cuda_bf16.h>
#include <math.h>
#include <stdint.h>

// Problem dims (fixed by the dataset)
#define BQ 64
#define SQ 512
#define DQ 768
#define CQ 512
#define MQ (BQ*SQ)   // 32768 tokens
#define ZCH 8        // s-chunks for partial z

// ---------------- scratch (device globals; no allocation allowed) ----------
__device__ __nv_bfloat16 g_Vn[(size_t)MQ * DQ];   // normalized V, bf16 (48 MB)
__device__ __nv_bfloat16 g_Ln[(size_t)CQ * DQ];   // normalized labels, bf16
__device__ unsigned      g_mkey[MQ];              // ordered-uint encoded row max
__device__ float         g_zpart[BQ * ZCH * DQ];  // partial z sums
__device__ float         g_z[BQ * DQ];            // z vectors

// ordered-uint encoding for float atomicMax (handles negatives)
__device__ __forceinline__ unsigned enc_f(float f) {
    unsigned u = __float_as_uint(f);
    return (u & 0x80000000u) ? ~u : (u | 0x80000000u);
}
__device__ __forceinline__ float dec_f(unsigned u) {
    return (u & 0x80000000u) ? __uint_as_float(u & 0x7fffffffu)
                             : __uint_as_float(~u);
}

// cp.async helpers
__device__ __forceinline__ void cpa16(void* smem, const void* g) {
    unsigned s = (unsigned)__cvta_generic_to_shared(smem);
    asm volatile("cp.async.cg.shared.global [%0], [%1], 16;\n" :: "r"(s), "l"(g));
}
#define CP_COMMIT() asm volatile("cp.async.commit_group;\n" ::: "memory")
#define CP_WAIT(n)  asm volatile("cp.async.wait_group %0;\n" :: "n"(n) : "memory")

__device__ __forceinline__ void ldsm_x4(unsigned& d0, unsigned& d1,
                                        unsigned& d2, unsigned& d3, const void* p) {
    unsigned a = (unsigned)__cvta_generic_to_shared(p);
    asm volatile("ldmatrix.sync.aligned.m8n8.x4.shared.b16 {%0,%1,%2,%3}, [%4];"
                 : "=r"(d0), "=r"(d1), "=r"(d2), "=r"(d3) : "r"(a));
}

// ---------------- kernel 1: row-normalize V and L in one grid --------------
// rows [0, MQ) -> V -> g_Vn (+ init g_mkey); rows [MQ, MQ+CQ) -> L -> g_Ln
__global__ void row_normalize_all(const float* __restrict__ V,
                                  const float* __restrict__ L) {
    int gw   = (blockIdx.x * blockDim.x + threadIdx.x) >> 5;
    int lane = threadIdx.x & 31;
    if (gw >= MQ + CQ) return;

    const bool isV = (gw < MQ);
    const float* src = isV ? (V + (size_t)gw * DQ)
                           : (L + (size_t)(gw - MQ) * DQ);
    __nv_bfloat16* out = isV ? (g_Vn + (size_t)gw * DQ)
                             : (g_Ln + (size_t)(gw - MQ) * DQ);

    const float4* r = (const float4*)src;
    float4 v[6];
    float ss = 0.f;
#pragma unroll
    for (int i = 0; i < 6; i++) {
        v[i] = r[lane + i * 32];
        ss += v[i].x * v[i].x + v[i].y * v[i].y + v[i].z * v[i].z + v[i].w * v[i].w;
    }
#pragma unroll
    for (int o = 16; o; o >>= 1) ss += __shfl_xor_sync(0xffffffffu, ss, o);
    float sc = 1.0f / fmaxf(sqrtf(ss), 1e-8f);

#pragma unroll
    for (int i = 0; i < 6; i++) {
        int base = (lane + i * 32) * 4;
        __nv_bfloat162 p0 = __floats2bfloat162_rn(v[i].x * sc, v[i].y * sc);
        __nv_bfloat162 p1 = __floats2bfloat162_rn(v[i].z * sc, v[i].w * sc);
        uint2 pk;
        pk.x = *(unsigned*)&p0;
        pk.y = *(unsigned*)&p1;
        *(uint2*)(out + base) = pk;
    }
    if (isV && lane == 0) g_mkey[gw] = 0u;
}

// ---------------- kernel 2: bf16 GEMM (Vn @ Ln^T) + row max ---------------
// CTA 128x128, BK=32, 4 warps (warp tile 64x64), occ 2, 3-stage cp.async
// pipeline with loads at iteration top, ldmatrix.x4 fragment loads.
#define GSTRIDE 40
#define GSTAGE  (128 * GSTRIDE)            // bf16 elems per matrix per stage
#define GK_SMEM (3 * 2 * GSTAGE * 2)       // 61440 bytes

__global__ __launch_bounds__(128, 2)
void gemm_rowmax_kernel() {
    extern __shared__ __nv_bfloat16 sm[];
    __nv_bfloat16* Asm = sm;                 // [3][128][40]
    __nv_bfloat16* Bsm = sm + 3 * GSTAGE;    // [3][128][40]
    __shared__ float rmax[128][2];

    const int bn = blockIdx.x;        // 0..3   (class tiles)
    const int bm = blockIdx.y;        // 0..255 (token tiles)
    const int t = threadIdx.x;        // 128 threads
    const int lane = t & 31, warp = t >> 5;
    const int wr = warp & 1, wc = warp >> 1;
    const int wm0 = wr * 64, wn0 = wc * 64;
    const int g = lane >> 2, tq = lane & 3;
    // ldmatrix lane mapping
    const int row8 = lane & 7, tile = lane >> 3;
    const int tA_r = (tile & 1) * 8, tA_c = (tile >> 1) * 8;
    const int tB_n = (tile >> 1) * 8, tB_c = (tile & 1) * 8;

    float acc[4][8][4];
#pragma unroll
    for (int mi = 0; mi < 4; mi++)
#pragma unroll
        for (int ni = 0; ni < 8; ni++)
#pragma unroll
            for (int q = 0; q < 4; q++) acc[mi][ni][q] = 0.f;

    const size_t a_base = (size_t)(bm * 128) * DQ;
    const size_t b_base = (size_t)(bn * 128) * DQ;

    // per-thread load mapping: 512 16B-chunks per matrix per stage, 4 per thread
    const int lrow[4] = { (t) >> 2, (t + 128) >> 2, (t + 256) >> 2, (t + 384) >> 2 };
    const int lci [4] = { (t) & 3,  (t + 128) & 3,  (t + 256) & 3,  (t + 384) & 3 };

    auto load_stage = [&](int st, int kt) {
        const int k0 = kt * 32;
        __nv_bfloat16* As = Asm + st * GSTAGE;
        __nv_bfloat16* Bs = Bsm + st * GSTAGE;
#pragma unroll
        for (int i = 0; i < 4; i++) {
            cpa16(&As[lrow[i] * GSTRIDE + lci[i] * 8],
                  &g_Vn[a_base + (size_t)lrow[i] * DQ + k0 + lci[i] * 8]);
            cpa16(&Bs[lrow[i] * GSTRIDE + lci[i] * 8],
                  &g_Ln[b_base + (size_t)lrow[i] * DQ + k0 + lci[i] * 8]);
        }
        CP_COMMIT();
    };

    const int NK = DQ / 32;           // 24
    load_stage(0, 0);
    load_stage(1, 1);

    for (int kt = 0; kt < NK; kt++) {
        const int cur = kt % 3;
        if (kt + 1 < NK) CP_WAIT(1); else CP_WAIT(0);
        __syncthreads();
        // issue next-next stage NOW: overlaps the whole compute below.
        // buffer (kt+2)%3 was last read in iter kt-1, ordered by the barrier.
        if (kt + 2 < NK) load_stage((kt + 2) % 3, kt + 2);

        const __nv_bfloat16* As = Asm + cur * GSTAGE;
        const __nv_bfloat16* Bs = Bsm + cur * GSTAGE;
#pragma unroll
        for (int kk = 0; kk < 32; kk += 16) {
            unsigned af[4][4], bf[8][2];
#pragma unroll
            for (int mi = 0; mi < 4; mi++) {
                ldsm_x4(af[mi][0], af[mi][1], af[mi][2], af[mi][3],
                        &As[(wm0 + mi * 16 + tA_r + row8) * GSTRIDE + kk + tA_c]);
            }
#pragma unroll
            for (int ni = 0; ni < 8; ni += 2) {
                ldsm_x4(bf[ni][0], bf[ni][1], bf[ni + 1][0], bf[ni + 1][1],
                        &Bs[(wn0 + ni * 8 + tB_n + row8) * GSTRIDE + kk + tB_c]);
            }
#pragma unroll
            for (int mi = 0; mi < 4; mi++)
#pragma unroll
                for (int ni = 0; ni < 8; ni++) {
                    asm volatile(
                        "mma.sync.aligned.m16n8k16.row.col.f32.bf16.bf16.f32 "
                        "{%0,%1,%2,%3}, {%4,%5,%6,%7}, {%8,%9}, {%0,%1,%2,%3};\n"
                        : "+f"(acc[mi][ni][0]), "+f"(acc[mi][ni][1]),
                          "+f"(acc[mi][ni][2]), "+f"(acc[mi][ni][3])
                        : "r"(af[mi][0]), "r"(af[mi][1]), "r"(af[mi][2]), "r"(af[mi][3]),
                          "r"(bf[ni][0]), "r"(bf[ni][1]));
                }
        }
    }

    // per-row max over this 128-class tile
#pragma unroll
    for (int mi = 0; mi < 4; mi++) {
        float lo = -INFINITY, hi = -INFINITY;
#pragma unroll
        for (int ni = 0; ni < 8; ni++) {
            lo = fmaxf(lo, fmaxf(acc[mi][ni][0], acc[mi][ni][1]));
            hi = fmaxf(hi, fmaxf(acc[mi][ni][2], acc[mi][ni][3]));
        }
        lo = fmaxf(lo, __shfl_xor_sync(0xffffffffu, lo, 1));
        lo = fmaxf(lo, __shfl_xor_sync(0xffffffffu, lo, 2));
        hi = fmaxf(hi, __shfl_xor_sync(0xffffffffu, hi, 1));
        hi = fmaxf(hi, __shfl_xor_sync(0xffffffffu, hi, 2));
        if (tq == 0) {
            rmax[wm0 + mi * 16 + g][wc]     = lo;
            rmax[wm0 + mi * 16 + g + 8][wc] = hi;
        }
    }
    __syncthreads();
    if (t < 128) {
        float v = fmaxf(rmax[t][0], rmax[t][1]);
        atomicMax(&g_mkey[bm * 128 + t], enc_f(v));
    }
}

// ---------------- kernel 3: fused softmax + partial z ----------------------
// grid (B, ZCH), 256 thr; each CTA recomputes the cheap per-batch softmax,
// then accumulates its 64-row chunk of z with coalesced V reads.
__global__ void zpart_kernel(const float* __restrict__ V) {
    __shared__ float bsm[SQ / ZCH];
    __shared__ float red[8];
    const int b = blockIdx.x, ch = blockIdx.y;
    const int t = threadIdx.x;
    const int lane = t & 31, wid = t >> 5;
    constexpr int RS = SQ / ZCH;   // 64 rows per chunk

    // softmax over all 512 tokens of batch b (each thread holds 2)
    float m0 = dec_f(g_mkey[b * SQ + t]);
    float m1 = dec_f(g_mkey[b * SQ + t + 256]);
    float lm = fmaxf(m0, m1);
#pragma unroll
    for (int o = 16; o; o >>= 1) lm = fmaxf(lm, __shfl_xor_sync(0xffffffffu, lm, o));
    if (lane == 0) red[wid] = lm;
    __syncthreads();
    float M = red[0];
#pragma unroll
    for (int i = 1; i < 8; i++) M = fmaxf(M, red[i]);
    __syncthreads();

    float ls = expf(m0 - M) + expf(m1 - M);
#pragma unroll
    for (int o = 16; o; o >>= 1) ls += __shfl_xor_sync(0xffffffffu, ls, o);
    if (lane == 0) red[wid] = ls;
    __syncthreads();
    float S = 0.f;
#pragma unroll
    for (int i = 0; i < 8; i++) S += red[i];
    float invS = 1.f / S;

    if (t < RS) {
        float mm = dec_f(g_mkey[b * SQ + ch * RS + t]);
        bsm[t] = expf(mm - M) * invS;
    }
    __syncthreads();

    const float* Vb = V + ((size_t)b * SQ + ch * RS) * DQ;
    float a0 = 0.f, a1 = 0.f, a2 = 0.f;
#pragma unroll 4
    for (int r = 0; r < RS; r++) {
        float be = bsm[r];
        const float* row = Vb + (size_t)r * DQ;
        a0 += be * row[t];
        a1 += be * row[t + 256];
        a2 += be * row[t + 512];
    }
    float* zp = g_zpart + (size_t)(b * ZCH + ch) * DQ;
    zp[t]       = a0;
    zp[t + 256] = a1;
    zp[t + 512] = a2;
}

// ---------------- kernel 4: combine partials -> z --------------------------
__global__ void zcombine_kernel(float* __restrict__ zout) {
    const int b = blockIdx.x;
    const int t = threadIdx.x;   // 256
#pragma unroll
    for (int j = 0; j < 3; j++) {
        int d = t + j * 256;
        float s = 0.f;
#pragma unroll
        for (int c = 0; c < ZCH; c++) s += g_zpart[(size_t)(b * ZCH + c) * DQ + d];
        g_z[b * DQ + d] = s;
        if (zout) zout[b * DQ + d] = s;
    }
}

// ---------------- kernel 5: out = z @ fc_w^T + fc_b ------------------------
__global__ void fc_kernel(const float* __restrict__ fc_w, const float* __restrict__ fc_b,
                          float* __restrict__ out) {
    const int t = threadIdx.x;
    const int lane = t & 31;
    const int gw = (blockIdx.x * blockDim.x + t) >> 5;
    if (gw >= BQ * CQ) return;
    const int b = gw >> 9;
    const int c = gw & 511;
    const float4* wr = (const float4*)(fc_w + (size_t)c * DQ);
    const float4* zr = (const float4*)(g_z + b * DQ);
    float acc = 0.f;
#pragma unroll
    for (int i = 0; i < 6; i++) {
        float4 wv = wr[lane + i * 32];
        float4 zv = zr[lane + i * 32];
        acc += wv.x * zv.x + wv.y * zv.y + wv.z * zv.z + wv.w * zv.w;
    }
#pragma unroll
    for (int o = 16; o; o >>= 1) acc += __shfl_xor_sync(0xffffffffu, acc, o);
    if (lane == 0) out[b * CQ + c] = acc + fc_b[c];
}

// ---------------- launch ----------------------------------------------------
extern "C" void kernel_launch(void* const* d_in, const int* in_sizes, int n_in,
                              void* d_out, int out_size) {
    const float* V  = (const float*)d_in[0];
    const float* L  = (const float*)d_in[1];
    const float* fw = (const float*)d_in[2];
    const float* fb = (const float*)d_in[3];
    float* out = (float*)d_out;
    float* zout = (out_size >= BQ * CQ + BQ * DQ) ? (out + BQ * CQ) : nullptr;

    static int smem_set = 0;
    if (!smem_set) {
        cudaFuncSetAttribute(gemm_rowmax_kernel,
                             cudaFuncAttributeMaxDynamicSharedMemorySize, GK_SMEM);
        smem_set = 1;
    }

    row_normalize_all<<<(MQ + CQ) / 8, 256>>>(V, L);
    gemm_rowmax_kernel<<<dim3(CQ / 128, MQ / 128), 128, GK_SMEM>>>();
    zpart_kernel<<<dim3(BQ, ZCH), 256>>>(V);
    zcombine_kernel<<<BQ, 256>>>(zout);
    fc_kernel<<<(BQ * CQ * 32) / 256, 256>>>(fw, fb, out);
}

// round 7
// speedup vs baseline: 1.1411x; 1.0131x over previous
#include <cuda_runtime.h>
#include <cuda_bf16.h>
#include <math.h>
#include <stdint.h>

// Problem dims (fixed by the dataset)
#define BQ 64
#define SQ 512
#define DQ 768
#define CQ 512
#define MQ (BQ*SQ)   // 32768 tokens
#define ZCH 8        // s-chunks for partial z

// ---------------- scratch (device globals; no allocation allowed) ----------
__device__ __nv_bfloat16 g_Vn[(size_t)MQ * DQ];   // normalized V, bf16 (48 MB)
__device__ __nv_bfloat16 g_Ln[(size_t)CQ * DQ];   // normalized labels, bf16
__device__ unsigned      g_mkey[MQ];              // ordered-uint encoded row max
__device__ float         g_zpart[BQ * ZCH * DQ];  // partial z sums
__device__ float         g_z[BQ * DQ];            // z vectors

// ordered-uint encoding for float atomicMax (handles negatives)
__device__ __forceinline__ unsigned enc_f(float f) {
    unsigned u = __float_as_uint(f);
    return (u & 0x80000000u) ? ~u : (u | 0x80000000u);
}
__device__ __forceinline__ float dec_f(unsigned u) {
    return (u & 0x80000000u) ? __uint_as_float(u & 0x7fffffffu)
                             : __uint_as_float(~u);
}

// cp.async helpers
__device__ __forceinline__ void cpa16(void* smem, const void* g) {
    unsigned s = (unsigned)__cvta_generic_to_shared(smem);
    asm volatile("cp.async.cg.shared.global [%0], [%1], 16;\n" :: "r"(s), "l"(g));
}
#define CP_COMMIT() asm volatile("cp.async.commit_group;\n" ::: "memory")
#define CP_WAIT(n)  asm volatile("cp.async.wait_group %0;\n" :: "n"(n) : "memory")

__device__ __forceinline__ void ldsm_x4(unsigned& d0, unsigned& d1,
                                        unsigned& d2, unsigned& d3, const void* p) {
    unsigned a = (unsigned)__cvta_generic_to_shared(p);
    asm volatile("ldmatrix.sync.aligned.m8n8.x4.shared.b16 {%0,%1,%2,%3}, [%4];"
                 : "=r"(d0), "=r"(d1), "=r"(d2), "=r"(d3) : "r"(a));
}

// ---------------- kernel 1: row-normalize V and L in one grid --------------
__global__ void row_normalize_all(const float* __restrict__ V,
                                  const float* __restrict__ L) {
    int gw   = (blockIdx.x * blockDim.x + threadIdx.x) >> 5;
    int lane = threadIdx.x & 31;
    if (gw >= MQ + CQ) return;

    const bool isV = (gw < MQ);
    const float* src = isV ? (V + (size_t)gw * DQ)
                           : (L + (size_t)(gw - MQ) * DQ);
    __nv_bfloat16* out = isV ? (g_Vn + (size_t)gw * DQ)
                             : (g_Ln + (size_t)(gw - MQ) * DQ);

    const float4* r = (const float4*)src;
    float4 v[6];
    float ss = 0.f;
#pragma unroll
    for (int i = 0; i < 6; i++) {
        v[i] = r[lane + i * 32];
        ss += v[i].x * v[i].x + v[i].y * v[i].y + v[i].z * v[i].z + v[i].w * v[i].w;
    }
#pragma unroll
    for (int o = 16; o; o >>= 1) ss += __shfl_xor_sync(0xffffffffu, ss, o);
    float sc = 1.0f / fmaxf(sqrtf(ss), 1e-8f);

#pragma unroll
    for (int i = 0; i < 6; i++) {
        int base = (lane + i * 32) * 4;
        __nv_bfloat162 p0 = __floats2bfloat162_rn(v[i].x * sc, v[i].y * sc);
        __nv_bfloat162 p1 = __floats2bfloat162_rn(v[i].z * sc, v[i].w * sc);
        uint2 pk;
        pk.x = *(unsigned*)&p0;
        pk.y = *(unsigned*)&p1;
        *(uint2*)(out + base) = pk;
    }
    if (isV && lane == 0) g_mkey[gw] = 0u;
}

// ---------------- kernel 2: bf16 GEMM (Vn @ Ln^T) + row max ---------------
// CTA 128x128, BK=64, 4 warps (warp tile 64x64), occ 2, 3-stage cp.async
// pipeline (loads at iteration top), ldmatrix.x4 with register
// double-buffered fragments. smem stride 72 bf16 -> conflict-free.
#define GSTRIDE 72
#define GSTAGE  (128 * GSTRIDE)            // bf16 elems per matrix per stage
#define GK_SMEM (3 * 2 * GSTAGE * 2)       // 110592 bytes

__global__ __launch_bounds__(128, 2)
void gemm_rowmax_kernel() {
    extern __shared__ __nv_bfloat16 sm[];
    __nv_bfloat16* Asm = sm;                 // [3][128][72]
    __nv_bfloat16* Bsm = sm + 3 * GSTAGE;    // [3][128][72]
    __shared__ float rmax[128][2];

    const int bn = blockIdx.x;        // 0..3   (class tiles)
    const int bm = blockIdx.y;        // 0..255 (token tiles)
    const int t = threadIdx.x;        // 128 threads
    const int lane = t & 31, warp = t >> 5;
    const int wr = warp & 1, wc = warp >> 1;
    const int wm0 = wr * 64, wn0 = wc * 64;
    const int g = lane >> 2, tq = lane & 3;
    // ldmatrix lane mapping
    const int row8 = lane & 7, tile = lane >> 3;
    const int tA_r = (tile & 1) * 8, tA_c = (tile >> 1) * 8;
    const int tB_n = (tile >> 1) * 8, tB_c = (tile & 1) * 8;

    float acc[4][8][4];
#pragma unroll
    for (int mi = 0; mi < 4; mi++)
#pragma unroll
        for (int ni = 0; ni < 8; ni++)
#pragma unroll
            for (int q = 0; q < 4; q++) acc[mi][ni][q] = 0.f;

    const size_t a_base = (size_t)(bm * 128) * DQ;
    const size_t b_base = (size_t)(bn * 128) * DQ;

    auto load_stage = [&](int st, int kt) {
        const int k0 = kt * 64;
        __nv_bfloat16* As = Asm + st * GSTAGE;
        __nv_bfloat16* Bs = Bsm + st * GSTAGE;
#pragma unroll
        for (int i = 0; i < 8; i++) {          // 1024 16B-chunks per matrix
            int idx = t + i * 128;
            int row = idx >> 3, ci = idx & 7;
            cpa16(&As[row * GSTRIDE + ci * 8],
                  &g_Vn[a_base + (size_t)row * DQ + k0 + ci * 8]);
            cpa16(&Bs[row * GSTRIDE + ci * 8],
                  &g_Ln[b_base + (size_t)row * DQ + k0 + ci * 8]);
        }
        CP_COMMIT();
    };

    const int NK = DQ / 64;           // 12
    load_stage(0, 0);
    load_stage(1, 1);

    for (int kt = 0; kt < NK; kt++) {
        const int cur = kt % 3;
        if (kt + 1 < NK) CP_WAIT(1); else CP_WAIT(0);
        __syncthreads();
        // issue stage kt+2 now: overlaps the whole compute below.
        if (kt + 2 < NK) load_stage((kt + 2) % 3, kt + 2);

        const __nv_bfloat16* As = Asm + cur * GSTAGE;
        const __nv_bfloat16* Bs = Bsm + cur * GSTAGE;

        unsigned af[2][4][4], bf[2][8][2];
        auto load_frags = [&](int fb, int kk) {
#pragma unroll
            for (int mi = 0; mi < 4; mi++) {
                ldsm_x4(af[fb][mi][0], af[fb][mi][1], af[fb][mi][2], af[fb][mi][3],
                        &As[(wm0 + mi * 16 + tA_r + row8) * GSTRIDE + kk + tA_c]);
            }
#pragma unroll
            for (int ni = 0; ni < 8; ni += 2) {
                ldsm_x4(bf[fb][ni][0], bf[fb][ni][1], bf[fb][ni + 1][0], bf[fb][ni + 1][1],
                        &Bs[(wn0 + ni * 8 + tB_n + row8) * GSTRIDE + kk + tB_c]);
            }
        };

        load_frags(0, 0);
#pragma unroll
        for (int ks = 0; ks < 4; ks++) {
            const int fb = ks & 1;
            if (ks < 3) load_frags(fb ^ 1, (ks + 1) * 16);
#pragma unroll
            for (int mi = 0; mi < 4; mi++)
#pragma unroll
                for (int ni = 0; ni < 8; ni++) {
                    asm volatile(
                        "mma.sync.aligned.m16n8k16.row.col.f32.bf16.bf16.f32 "
                        "{%0,%1,%2,%3}, {%4,%5,%6,%7}, {%8,%9}, {%0,%1,%2,%3};\n"
                        : "+f"(acc[mi][ni][0]), "+f"(acc[mi][ni][1]),
                          "+f"(acc[mi][ni][2]), "+f"(acc[mi][ni][3])
                        : "r"(af[fb][mi][0]), "r"(af[fb][mi][1]),
                          "r"(af[fb][mi][2]), "r"(af[fb][mi][3]),
                          "r"(bf[fb][ni][0]), "r"(bf[fb][ni][1]));
                }
        }
    }

    // per-row max over this 128-class tile
#pragma unroll
    for (int mi = 0; mi < 4; mi++) {
        float lo = -INFINITY, hi = -INFINITY;
#pragma unroll
        for (int ni = 0; ni < 8; ni++) {
            lo = fmaxf(lo, fmaxf(acc[mi][ni][0], acc[mi][ni][1]));
            hi = fmaxf(hi, fmaxf(acc[mi][ni][2], acc[mi][ni][3]));
        }
        lo = fmaxf(lo, __shfl_xor_sync(0xffffffffu, lo, 1));
        lo = fmaxf(lo, __shfl_xor_sync(0xffffffffu, lo, 2));
        hi = fmaxf(hi, __shfl_xor_sync(0xffffffffu, hi, 1));
        hi = fmaxf(hi, __shfl_xor_sync(0xffffffffu, hi, 2));
        if (tq == 0) {
            rmax[wm0 + mi * 16 + g][wc]     = lo;
            rmax[wm0 + mi * 16 + g + 8][wc] = hi;
        }
    }
    __syncthreads();
    if (t < 128) {
        float v = fmaxf(rmax[t][0], rmax[t][1]);
        atomicMax(&g_mkey[bm * 128 + t], enc_f(v));
    }
}

// ---------------- kernel 3: fused softmax + partial z ----------------------
__global__ void zpart_kernel(const float* __restrict__ V) {
    __shared__ float bsm[SQ / ZCH];
    __shared__ float red[8];
    const int b = blockIdx.x, ch = blockIdx.y;
    const int t = threadIdx.x;
    const int lane = t & 31, wid = t >> 5;
    constexpr int RS = SQ / ZCH;   // 64 rows per chunk

    float m0 = dec_f(g_mkey[b * SQ + t]);
    float m1 = dec_f(g_mkey[b * SQ + t + 256]);
    float lm = fmaxf(m0, m1);
#pragma unroll
    for (int o = 16; o; o >>= 1) lm = fmaxf(lm, __shfl_xor_sync(0xffffffffu, lm, o));
    if (lane == 0) red[wid] = lm;
    __syncthreads();
    float M = red[0];
#pragma unroll
    for (int i = 1; i < 8; i++) M = fmaxf(M, red[i]);
    __syncthreads();

    float ls = expf(m0 - M) + expf(m1 - M);
#pragma unroll
    for (int o = 16; o; o >>= 1) ls += __shfl_xor_sync(0xffffffffu, ls, o);
    if (lane == 0) red[wid] = ls;
    __syncthreads();
    float S = 0.f;
#pragma unroll
    for (int i = 0; i < 8; i++) S += red[i];
    float invS = 1.f / S;

    if (t < RS) {
        float mm = dec_f(g_mkey[b * SQ + ch * RS + t]);
        bsm[t] = expf(mm - M) * invS;
    }
    __syncthreads();

    const float* Vb = V + ((size_t)b * SQ + ch * RS) * DQ;
    float a0 = 0.f, a1 = 0.f, a2 = 0.f;
#pragma unroll 4
    for (int r = 0; r < RS; r++) {
        float be = bsm[r];
        const float* row = Vb + (size_t)r * DQ;
        a0 += be * row[t];
        a1 += be * row[t + 256];
        a2 += be * row[t + 512];
    }
    float* zp = g_zpart + (size_t)(b * ZCH + ch) * DQ;
    zp[t]       = a0;
    zp[t + 256] = a1;
    zp[t + 512] = a2;
}

// ---------------- kernel 4: combine partials -> z (wide grid) --------------
__global__ void zcombine_kernel(float* __restrict__ zout) {
    const int b = blockIdx.x;
    const int d = blockIdx.y * 256 + threadIdx.x;   // grid.y = 3
    float s = 0.f;
#pragma unroll
    for (int c = 0; c < ZCH; c++) s += g_zpart[(size_t)(b * ZCH + c) * DQ + d];
    g_z[b * DQ + d] = s;
    if (zout) zout[b * DQ + d] = s;
}

// ---------------- kernel 5: out = z @ fc_w^T + fc_b ------------------------
__global__ void fc_kernel(const float* __restrict__ fc_w, const float* __restrict__ fc_b,
                          float* __restrict__ out) {
    const int t = threadIdx.x;
    const int lane = t & 31;
    const int gw = (blockIdx.x * blockDim.x + t) >> 5;
    if (gw >= BQ * CQ) return;
    const int b = gw >> 9;
    const int c = gw & 511;
    const float4* wr = (const float4*)(fc_w + (size_t)c * DQ);
    const float4* zr = (const float4*)(g_z + b * DQ);
    float acc = 0.f;
#pragma unroll
    for (int i = 0; i < 6; i++) {
        float4 wv = wr[lane + i * 32];
        float4 zv = zr[lane + i * 32];
        acc += wv.x * zv.x + wv.y * zv.y + wv.z * zv.z + wv.w * zv.w;
    }
#pragma unroll
    for (int o = 16; o; o >>= 1) acc += __shfl_xor_sync(0xffffffffu, acc, o);
    if (lane == 0) out[b * CQ + c] = acc + fc_b[c];
}

// ---------------- launch ----------------------------------------------------
extern "C" void kernel_launch(void* const* d_in, const int* in_sizes, int n_in,
                              void* d_out, int out_size) {
    const float* V  = (const float*)d_in[0];
    const float* L  = (const float*)d_in[1];
    const float* fw = (const float*)d_in[2];
    const float* fb = (const float*)d_in[3];
    float* out = (float*)d_out;
    float* zout = (out_size >= BQ * CQ + BQ * DQ) ? (out + BQ * CQ) : nullptr;

    static int smem_set = 0;
    if (!smem_set) {
        cudaFuncSetAttribute(gemm_rowmax_kernel,
                             cudaFuncAttributeMaxDynamicSharedMemorySize, GK_SMEM);
        smem_set = 1;
    }

    row_normalize_all<<<(MQ + CQ) / 8, 256>>>(V, L);
    gemm_rowmax_kernel<<<dim3(CQ / 128, MQ / 128), 128, GK_SMEM>>>();
    zpart_kernel<<<dim3(BQ, ZCH), 256>>>(V);
    zcombine_kernel<<<dim3(BQ, 3), 256>>>(zout);
    fc_kernel<<<(BQ * CQ * 32) / 256, 256>>>(fw, fb, out);
}